// round 1
// baseline (speedup 1.0000x reference)
#include <cuda_runtime.h>
#include <math.h>

// Problem constants (from reference): N=50000, E=800000, C_IN=128, C_HID=128, C_OUT=64
#define CIN  128
#define CHID 128
#define COUT 64
#define MAXN 50048
#define MAXE 800000

// -------- scratch (device globals; no runtime allocation allowed) --------
__device__ float g_deg[MAXN];
__device__ float g_dinv[MAXN];
__device__ int   g_cnt[MAXN];
__device__ int   g_off[MAXN + 1];
__device__ int   g_cur[MAXN];
__device__ int   g_csr_src[MAXE];
__device__ float g_csr_norm[MAXE];
__device__ float g_xw1[(size_t)MAXN * CHID];   // x @ W1
__device__ float g_h  [(size_t)MAXN * CHID];   // elu(conv1)
__device__ float g_xw2[(size_t)MAXN * COUT];   // h @ W2
__device__ int   g_idx64;

// -------- edge-index width detection (int64 vs int32), on-device --------
__global__ void k_detect(const int* __restrict__ ei, int words) {
    if (blockIdx.x == 0 && threadIdx.x == 0) {
        int all0 = 1;
        for (int i = 1; i < 256 && i < words; i += 2)
            if (ei[i] != 0) { all0 = 0; break; }
        g_idx64 = all0;  // little-endian int64 with small positive values => odd words all zero
    }
}

__device__ __forceinline__ void edge_sd(const void* ei, int E, int e, int& s, int& d) {
    if (g_idx64) {
        const long long* p = (const long long*)ei;
        s = (int)p[e];
        d = (int)p[(size_t)E + e];
    } else {
        const int* p = (const int*)ei;
        s = p[e];
        d = p[E + e];
    }
}

// -------- degree / CSR construction --------
__global__ void k_zero(int n) {
    int i = blockIdx.x * blockDim.x + threadIdx.x;
    if (i < n) { g_deg[i] = 0.0f; g_cnt[i] = 0; }
}

__global__ void k_deg_count(const void* __restrict__ ei, const float* __restrict__ ew, int E) {
    int e = blockIdx.x * blockDim.x + threadIdx.x;
    if (e >= E) return;
    int s, d;
    edge_sd(ei, E, e, s, d);
    atomicAdd(&g_deg[d], ew[e]);
    atomicAdd(&g_cnt[d], 1);
}

__global__ void k_dinv(int n) {
    int i = blockIdx.x * blockDim.x + threadIdx.x;
    if (i < n) g_dinv[i] = rsqrtf(g_deg[i] + 1.0f);  // +1 self loop => deg > 0 always
}

// Single-block exclusive scan of g_cnt -> g_off (and g_cur copy). 1024 threads.
__global__ void k_scan(int n) {
    __shared__ int sh[1024];
    int tid = threadIdx.x;
    int carry = 0;
    for (int base = 0; base < n; base += 1024) {
        int i = base + tid;
        int v = (i < n) ? g_cnt[i] : 0;
        sh[tid] = v;
        __syncthreads();
        for (int s = 1; s < 1024; s <<= 1) {
            int t = (tid >= s) ? sh[tid - s] : 0;
            __syncthreads();
            sh[tid] += t;
            __syncthreads();
        }
        int inc = sh[tid];
        if (i < n) {
            int ex = carry + inc - v;
            g_off[i] = ex;
            g_cur[i] = ex;
        }
        int total = sh[1023];
        __syncthreads();
        carry += total;
    }
    if (tid == 0) g_off[n] = carry;
}

__global__ void k_scatter(const void* __restrict__ ei, const float* __restrict__ ew, int E) {
    int e = blockIdx.x * blockDim.x + threadIdx.x;
    if (e >= E) return;
    int s, d;
    edge_sd(ei, E, e, s, d);
    int pos = atomicAdd(&g_cur[d], 1);
    g_csr_src[pos]  = s;
    g_csr_norm[pos] = g_dinv[s] * ew[e] * g_dinv[d];
}

// -------- GEMM: Y[n,NC] = X[n,128] @ W[128,NC], register-blocked SIMT fp32 --------
template <int NC>
__launch_bounds__(256)
__global__ void k_gemm(const float* __restrict__ X, const float* __restrict__ W,
                       float* __restrict__ Y, int n) {
    const int K  = 128;
    const int TM = 64;
    const int KB = 32;
    const int CPT = NC / 16;  // cols per thread (8 for NC=128, 4 for NC=64)

    __shared__ float Ws[KB][NC];
    __shared__ float Xs[KB][TM + 4];  // +4 pad: float4-aligned rows, reduced STS conflicts

    int tid = threadIdx.x;
    int tx = tid & 15;   // column group
    int ty = tid >> 4;   // row group (16 groups x 4 rows)
    int row0 = blockIdx.x * TM;

    float acc[4][CPT];
#pragma unroll
    for (int i = 0; i < 4; i++)
#pragma unroll
        for (int j = 0; j < CPT; j++) acc[i][j] = 0.0f;

    int kk = tid & 31;
    int rb = tid >> 5;

    for (int kt = 0; kt < K; kt += KB) {
        // W tile: KB contiguous rows of NC floats
        {
            const float4* W4 = (const float4*)(W + (size_t)kt * NC);
            float4* Ws4 = (float4*)&Ws[0][0];
#pragma unroll
            for (int i = tid; i < KB * NC / 4; i += 256) Ws4[i] = W4[i];
        }
        // X tile, transposed into Xs[k][r]
#pragma unroll
        for (int j = 0; j < TM / 8; j++) {
            int r = rb + j * 8;
            int row = row0 + r;
            Xs[kk][r] = (row < n) ? X[(size_t)row * K + kt + kk] : 0.0f;
        }
        __syncthreads();

#pragma unroll
        for (int k = 0; k < KB; k++) {
            float4 xv = *(const float4*)&Xs[k][ty * 4];
            float xr[4] = {xv.x, xv.y, xv.z, xv.w};
            float wv[CPT];
#pragma unroll
            for (int j = 0; j < CPT; j += 4) {
                float4 w4 = *(const float4*)&Ws[k][tx * CPT + j];
                wv[j] = w4.x; wv[j + 1] = w4.y; wv[j + 2] = w4.z; wv[j + 3] = w4.w;
            }
#pragma unroll
            for (int i = 0; i < 4; i++)
#pragma unroll
                for (int j = 0; j < CPT; j++) acc[i][j] = fmaf(xr[i], wv[j], acc[i][j]);
        }
        __syncthreads();
    }

#pragma unroll
    for (int i = 0; i < 4; i++) {
        int row = row0 + ty * 4 + i;
        if (row < n) {
#pragma unroll
            for (int j = 0; j < CPT; j += 4) {
                float4 o = {acc[i][j], acc[i][j + 1], acc[i][j + 2], acc[i][j + 3]};
                *(float4*)&Y[(size_t)row * NC + tx * CPT + j] = o;
            }
        }
    }
}

// -------- layer-1 aggregation (128 ch): warp per node, lane = one float4 --------
__launch_bounds__(256)
__global__ void k_agg1(const float* __restrict__ b1, int n) {
    int gw = (blockIdx.x * 256 + threadIdx.x) >> 5;
    int lane = threadIdx.x & 31;
    if (gw >= n) return;

    const float4* xw = (const float4*)g_xw1;  // node row = 32 float4s
    int beg = g_off[gw], end = g_off[gw + 1];

    float ax = 0.f, ay = 0.f, az = 0.f, aw = 0.f;
    int e = beg;
    for (; e + 2 <= end; e += 2) {
        int   s0 = g_csr_src[e],     s1 = g_csr_src[e + 1];
        float w0 = g_csr_norm[e],    w1 = g_csr_norm[e + 1];
        float4 v0 = xw[(size_t)s0 * 32 + lane];
        float4 v1 = xw[(size_t)s1 * 32 + lane];
        ax += w0 * v0.x + w1 * v1.x;
        ay += w0 * v0.y + w1 * v1.y;
        az += w0 * v0.z + w1 * v1.z;
        aw += w0 * v0.w + w1 * v1.w;
    }
    if (e < end) {
        int s = g_csr_src[e];
        float w = g_csr_norm[e];
        float4 v = xw[(size_t)s * 32 + lane];
        ax += w * v.x; ay += w * v.y; az += w * v.z; aw += w * v.w;
    }
    // self loop: norm = dinv[d]^2, weight 1
    float di = g_dinv[gw];
    float sn = di * di;
    float4 vs = xw[(size_t)gw * 32 + lane];
    ax += sn * vs.x; ay += sn * vs.y; az += sn * vs.z; aw += sn * vs.w;

    float4 bb = ((const float4*)b1)[lane];
    ax += bb.x; ay += bb.y; az += bb.z; aw += bb.w;

    float4 o;
    o.x = (ax > 0.f) ? ax : expm1f(ax);
    o.y = (ay > 0.f) ? ay : expm1f(ay);
    o.z = (az > 0.f) ? az : expm1f(az);
    o.w = (aw > 0.f) ? aw : expm1f(aw);
    ((float4*)g_h)[(size_t)gw * 32 + lane] = o;
}

// -------- layer-2 aggregation (64 ch): warp per node, lane = one float2 --------
__device__ __forceinline__ float softplus_f(float v) {
    return fmaxf(v, 0.0f) + log1pf(expf(-fabsf(v)));
}

__launch_bounds__(256)
__global__ void k_agg2(const float* __restrict__ b2, float* __restrict__ out, int n) {
    int gw = (blockIdx.x * 256 + threadIdx.x) >> 5;
    int lane = threadIdx.x & 31;
    if (gw >= n) return;

    const float2* xw = (const float2*)g_xw2;  // node row = 32 float2s
    int beg = g_off[gw], end = g_off[gw + 1];

    float ax = 0.f, ay = 0.f;
    int e = beg;
    for (; e + 2 <= end; e += 2) {
        int   s0 = g_csr_src[e],  s1 = g_csr_src[e + 1];
        float w0 = g_csr_norm[e], w1 = g_csr_norm[e + 1];
        float2 v0 = xw[(size_t)s0 * 32 + lane];
        float2 v1 = xw[(size_t)s1 * 32 + lane];
        ax += w0 * v0.x + w1 * v1.x;
        ay += w0 * v0.y + w1 * v1.y;
    }
    if (e < end) {
        int s = g_csr_src[e];
        float w = g_csr_norm[e];
        float2 v = xw[(size_t)s * 32 + lane];
        ax += w * v.x; ay += w * v.y;
    }
    float di = g_dinv[gw];
    float sn = di * di;
    float2 vs = xw[(size_t)gw * 32 + lane];
    ax += sn * vs.x; ay += sn * vs.y;

    float2 bb = ((const float2*)b2)[lane];
    ax += bb.x; ay += bb.y;

    float2 o;
    o.x = softplus_f(ax) + 1e-4f;
    o.y = softplus_f(ay) + 1e-4f;
    ((float2*)out)[(size_t)gw * 32 + lane] = o;
}

// -------- launcher --------
extern "C" void kernel_launch(void* const* d_in, const int* in_sizes, int n_in,
                              void* d_out, int out_size) {
    const float* x  = (const float*)d_in[0];
    const void*  ei = d_in[1];
    const float* ew = (const float*)d_in[2];
    const float* W1 = (const float*)d_in[3];
    const float* b1 = (const float*)d_in[4];
    const float* W2 = (const float*)d_in[5];
    const float* b2 = (const float*)d_in[6];
    float* out = (float*)d_out;

    int n = in_sizes[0] / CIN;   // 50000
    int E = in_sizes[2];         // 800000

    float *xw1p, *hp, *xw2p;
    cudaGetSymbolAddress((void**)&xw1p, g_xw1);
    cudaGetSymbolAddress((void**)&hp,   g_h);
    cudaGetSymbolAddress((void**)&xw2p, g_xw2);

    int nb = (n + 255) / 256;
    int eb = (E + 255) / 256;
    int ab = (n * 32 + 255) / 256;
    int gb = (n + 63) / 64;

    k_detect<<<1, 32>>>((const int*)ei, 2 * E);
    k_zero<<<nb, 256>>>(n);
    k_deg_count<<<eb, 256>>>(ei, ew, E);
    k_dinv<<<nb, 256>>>(n);
    k_scan<<<1, 1024>>>(n);
    k_scatter<<<eb, 256>>>(ei, ew, E);

    k_gemm<CHID><<<gb, 256>>>(x, W1, xw1p, n);
    k_agg1<<<ab, 256>>>(b1, n);
    k_gemm<COUT><<<gb, 256>>>(hp, W2, xw2p, n);
    k_agg2<<<ab, 256>>>(b2, out, n);
}

// round 3
// speedup vs baseline: 1.4563x; 1.4563x over previous
#include <cuda_runtime.h>
#include <math.h>

// N=50000, E=800000, C_IN=128, C_HID=128, C_OUT=64
#define CIN  128
#define CHID 128
#define COUT 64
#define MAXN 50048
#define MAXE 800000
#define MAXB 256   // max scan blocks (ceil(50048/256) = 196)

// -------- scratch (device globals) --------
__device__ float g_deg[MAXN];
__device__ float g_dinv[MAXN];
__device__ int   g_cnt[MAXN];
__device__ int   g_off[MAXN + 1];
__device__ int   g_cur[MAXN];
__device__ int   g_part[MAXB];
__device__ int   g_pbase[MAXB];
__device__ int   g_csr_src[MAXE];
__device__ float g_csr_norm[MAXE];
__device__ float g_xw1[(size_t)MAXN * CHID];
__device__ float g_h  [(size_t)MAXN * CHID];
__device__ float g_xw2[(size_t)MAXN * COUT];
__device__ int   g_idx64;

// -------- zero + warp-parallel edge-index width detection --------
__global__ void k_zero(const int* __restrict__ ei, int words, int n) {
    int i = blockIdx.x * blockDim.x + threadIdx.x;
    if (i < n) { g_deg[i] = 0.0f; g_cnt[i] = 0; }
    // int64 detection: little-endian int64 with small positive values => odd words zero
    if (blockIdx.x == 0 && threadIdx.x < 32) {
        int t = threadIdx.x;
        int i1 = 1 + 2 * t, i2 = 65 + 2 * t;
        int nz = 0;
        if (i1 < words && ei[i1] != 0) nz = 1;
        if (i2 < words && ei[i2] != 0) nz = 1;
        unsigned b = __ballot_sync(0xFFFFFFFFu, nz);
        if (t == 0) g_idx64 = (b == 0u) ? 1 : 0;
    }
}

__device__ __forceinline__ void edge_sd(const void* ei, int E, int e, int& s, int& d) {
    if (g_idx64) {
        const long long* p = (const long long*)ei;
        s = (int)p[e];
        d = (int)p[(size_t)E + e];
    } else {
        const int* p = (const int*)ei;
        s = p[e];
        d = p[E + e];
    }
}

__global__ void k_deg_count(const void* __restrict__ ei, const float* __restrict__ ew, int E) {
    int e = blockIdx.x * blockDim.x + threadIdx.x;
    if (e >= E) return;
    int s, d;
    edge_sd(ei, E, e, s, d);
    atomicAdd(&g_deg[d], ew[e]);
    atomicAdd(&g_cnt[d], 1);
}

// -------- parallel scan: block partial sums --------
__global__ void k_scan_part(int n) {
    __shared__ int sh[8];
    int i = blockIdx.x * 256 + threadIdx.x;
    int v = (i < n) ? g_cnt[i] : 0;
    int lane = threadIdx.x & 31, wid = threadIdx.x >> 5;
    int s = v;
#pragma unroll
    for (int o = 1; o < 32; o <<= 1) {
        int t = __shfl_up_sync(0xFFFFFFFFu, s, o);
        if (lane >= o) s += t;
    }
    if (lane == 31) sh[wid] = s;
    __syncthreads();
    if (threadIdx.x == 0) {
        int tot = 0;
#pragma unroll
        for (int w = 0; w < 8; w++) tot += sh[w];
        g_part[blockIdx.x] = tot;
    }
}

// -------- scan the (<=256) partials, one block --------
__global__ void k_scan_top(int nb) {
    int tid = threadIdx.x;
    int v = (tid < nb) ? g_part[tid] : 0;
    int lane = tid & 31, wid = tid >> 5;
    int s = v;
#pragma unroll
    for (int o = 1; o < 32; o <<= 1) {
        int t = __shfl_up_sync(0xFFFFFFFFu, s, o);
        if (lane >= o) s += t;
    }
    __shared__ int wsum[8];
    if (lane == 31) wsum[wid] = s;
    __syncthreads();
    __shared__ int wbase[8];
    if (tid == 0) {
        int acc = 0;
#pragma unroll
        for (int w = 0; w < 8; w++) { wbase[w] = acc; acc += wsum[w]; }
    }
    __syncthreads();
    if (tid < nb) g_pbase[tid] = wbase[wid] + s - v;   // exclusive
}

// -------- downsweep: g_off/g_cur, fused dinv --------
__global__ void k_downsweep(int n, int E) {
    __shared__ int wsum[8], wbase[8];
    int i = blockIdx.x * 256 + threadIdx.x;
    int v = (i < n) ? g_cnt[i] : 0;
    int lane = threadIdx.x & 31, wid = threadIdx.x >> 5;
    int s = v;
#pragma unroll
    for (int o = 1; o < 32; o <<= 1) {
        int t = __shfl_up_sync(0xFFFFFFFFu, s, o);
        if (lane >= o) s += t;
    }
    if (lane == 31) wsum[wid] = s;
    __syncthreads();
    if (threadIdx.x == 0) {
        int acc = 0;
#pragma unroll
        for (int w = 0; w < 8; w++) { wbase[w] = acc; acc += wsum[w]; }
    }
    __syncthreads();
    if (i < n) {
        int ex = g_pbase[blockIdx.x] + wbase[wid] + s - v;
        g_off[i] = ex;
        g_cur[i] = ex;
        g_dinv[i] = rsqrtf(g_deg[i] + 1.0f);   // +1 self loop
    }
    if (i == 0) g_off[n] = E;
}

__global__ void k_scatter(const void* __restrict__ ei, const float* __restrict__ ew, int E) {
    int e = blockIdx.x * blockDim.x + threadIdx.x;
    if (e >= E) return;
    int s, d;
    edge_sd(ei, E, e, s, d);
    int pos = atomicAdd(&g_cur[d], 1);
    g_csr_src[pos]  = s;
    g_csr_norm[pos] = g_dinv[s] * ew[e] * g_dinv[d];
}

// -------- GEMM: Y[n,NC] = X[n,128] @ W[128,NC]; 128xNC tile, 8x(NC/16) per thread --------
template <int NC>
__launch_bounds__(256, 2)
__global__ void k_gemm(const float* __restrict__ X, const float* __restrict__ W,
                       float* __restrict__ Y, int n) {
    const int K  = 128;
    const int KB = 32;
    const int NG = NC / 64;            // column groups of 64 (2 for 128, 1 for 64)

    __shared__ float Ws[KB][NC];
    __shared__ float Xs[KB][132];      // [k][r], stride 132 (16B aligned, de-conflicted)

    int tid = threadIdx.x;
    int tx = tid & 15;                 // column lane: cols g*64 + tx*4 .. +3
    int ty = tid >> 4;                 // row group: rows ty*8 .. +7
    int row0 = blockIdx.x * 128;

    float acc[8][NG * 4];
#pragma unroll
    for (int i = 0; i < 8; i++)
#pragma unroll
        for (int j = 0; j < NG * 4; j++) acc[i][j] = 0.0f;

    for (int kt = 0; kt < K; kt += KB) {
        // W tile
        {
            const float4* W4 = (const float4*)(W + (size_t)kt * NC);
            float4* Ws4 = (float4*)&Ws[0][0];
#pragma unroll
            for (int i = tid; i < KB * NC / 4; i += 256) Ws4[i] = W4[i];
        }
        // X tile (transposed): 128 rows x 8 float4 each
#pragma unroll
        for (int i = 0; i < 4; i++) {
            int idx = tid + 256 * i;
            int r = idx >> 3, c = idx & 7;
            int row = row0 + r;
            float4 v = make_float4(0.f, 0.f, 0.f, 0.f);
            if (row < n) v = *(const float4*)&X[(size_t)row * K + kt + 4 * c];
            Xs[4 * c + 0][r] = v.x;
            Xs[4 * c + 1][r] = v.y;
            Xs[4 * c + 2][r] = v.z;
            Xs[4 * c + 3][r] = v.w;
        }
        __syncthreads();

#pragma unroll
        for (int k = 0; k < KB; k++) {
            float4 x0 = *(const float4*)&Xs[k][ty * 8];
            float4 x1 = *(const float4*)&Xs[k][ty * 8 + 4];
            float xr[8] = {x0.x, x0.y, x0.z, x0.w, x1.x, x1.y, x1.z, x1.w};
            float wv[NG * 4];
#pragma unroll
            for (int g = 0; g < NG; g++) {
                float4 w4 = *(const float4*)&Ws[k][g * 64 + tx * 4];
                wv[g * 4] = w4.x; wv[g * 4 + 1] = w4.y;
                wv[g * 4 + 2] = w4.z; wv[g * 4 + 3] = w4.w;
            }
#pragma unroll
            for (int i = 0; i < 8; i++)
#pragma unroll
                for (int j = 0; j < NG * 4; j++)
                    acc[i][j] = fmaf(xr[i], wv[j], acc[i][j]);
        }
        __syncthreads();
    }

#pragma unroll
    for (int i = 0; i < 8; i++) {
        int row = row0 + ty * 8 + i;
        if (row < n) {
#pragma unroll
            for (int g = 0; g < NG; g++) {
                float4 o = {acc[i][g * 4], acc[i][g * 4 + 1], acc[i][g * 4 + 2], acc[i][g * 4 + 3]};
                *(float4*)&Y[(size_t)row * NC + g * 64 + tx * 4] = o;
            }
        }
    }
}

// -------- layer-1 aggregation (128 ch): warp per node --------
__launch_bounds__(256)
__global__ void k_agg1(const float* __restrict__ b1, int n) {
    int gw = (blockIdx.x * 256 + threadIdx.x) >> 5;
    int lane = threadIdx.x & 31;
    if (gw >= n) return;

    const float4* __restrict__ xw = (const float4*)g_xw1;
    const int*   __restrict__ csr = g_csr_src;
    const float* __restrict__ nrm = g_csr_norm;
    int beg = g_off[gw], end = g_off[gw + 1];

    float ax = 0.f, ay = 0.f, az = 0.f, aw = 0.f;
    int e = beg;
    for (; e + 2 <= end; e += 2) {
        int   s0 = __ldg(&csr[e]),  s1 = __ldg(&csr[e + 1]);
        float w0 = __ldg(&nrm[e]),  w1 = __ldg(&nrm[e + 1]);
        float4 v0 = xw[(size_t)s0 * 32 + lane];
        float4 v1 = xw[(size_t)s1 * 32 + lane];
        ax += w0 * v0.x + w1 * v1.x;
        ay += w0 * v0.y + w1 * v1.y;
        az += w0 * v0.z + w1 * v1.z;
        aw += w0 * v0.w + w1 * v1.w;
    }
    if (e < end) {
        int s = __ldg(&csr[e]);
        float w = __ldg(&nrm[e]);
        float4 v = xw[(size_t)s * 32 + lane];
        ax += w * v.x; ay += w * v.y; az += w * v.z; aw += w * v.w;
    }
    float di = g_dinv[gw];
    float sn = di * di;
    float4 vs = xw[(size_t)gw * 32 + lane];
    ax += sn * vs.x; ay += sn * vs.y; az += sn * vs.z; aw += sn * vs.w;

    float4 bb = ((const float4*)b1)[lane];
    ax += bb.x; ay += bb.y; az += bb.z; aw += bb.w;

    float4 o;
    o.x = (ax > 0.f) ? ax : expm1f(ax);
    o.y = (ay > 0.f) ? ay : expm1f(ay);
    o.z = (az > 0.f) ? az : expm1f(az);
    o.w = (aw > 0.f) ? aw : expm1f(aw);
    ((float4*)g_h)[(size_t)gw * 32 + lane] = o;
}

// -------- layer-2 aggregation (64 ch) --------
__device__ __forceinline__ float softplus_f(float v) {
    return fmaxf(v, 0.0f) + log1pf(expf(-fabsf(v)));
}

__launch_bounds__(256)
__global__ void k_agg2(const float* __restrict__ b2, float* __restrict__ out, int n) {
    int gw = (blockIdx.x * 256 + threadIdx.x) >> 5;
    int lane = threadIdx.x & 31;
    if (gw >= n) return;

    const float2* __restrict__ xw = (const float2*)g_xw2;
    const int*   __restrict__ csr = g_csr_src;
    const float* __restrict__ nrm = g_csr_norm;
    int beg = g_off[gw], end = g_off[gw + 1];

    float ax = 0.f, ay = 0.f;
    int e = beg;
    for (; e + 2 <= end; e += 2) {
        int   s0 = __ldg(&csr[e]),  s1 = __ldg(&csr[e + 1]);
        float w0 = __ldg(&nrm[e]),  w1 = __ldg(&nrm[e + 1]);
        float2 v0 = xw[(size_t)s0 * 32 + lane];
        float2 v1 = xw[(size_t)s1 * 32 + lane];
        ax += w0 * v0.x + w1 * v1.x;
        ay += w0 * v0.y + w1 * v1.y;
    }
    if (e < end) {
        int s = __ldg(&csr[e]);
        float w = __ldg(&nrm[e]);
        float2 v = xw[(size_t)s * 32 + lane];
        ax += w * v.x; ay += w * v.y;
    }
    float di = g_dinv[gw];
    float sn = di * di;
    float2 vs = xw[(size_t)gw * 32 + lane];
    ax += sn * vs.x; ay += sn * vs.y;

    float2 bb = ((const float2*)b2)[lane];
    ax += bb.x; ay += bb.y;

    float2 o;
    o.x = softplus_f(ax) + 1e-4f;
    o.y = softplus_f(ay) + 1e-4f;
    ((float2*)out)[(size_t)gw * 32 + lane] = o;
}

// -------- launcher --------
extern "C" void kernel_launch(void* const* d_in, const int* in_sizes, int n_in,
                              void* d_out, int out_size) {
    const float* x  = (const float*)d_in[0];
    const void*  ei = d_in[1];
    const float* ew = (const float*)d_in[2];
    const float* W1 = (const float*)d_in[3];
    const float* b1 = (const float*)d_in[4];
    const float* W2 = (const float*)d_in[5];
    const float* b2 = (const float*)d_in[6];
    float* out = (float*)d_out;

    int n = in_sizes[0] / CIN;   // 50000
    int E = in_sizes[2];         // 800000

    float *xw1p, *hp, *xw2p;
    cudaGetSymbolAddress((void**)&xw1p, g_xw1);
    cudaGetSymbolAddress((void**)&hp,   g_h);
    cudaGetSymbolAddress((void**)&xw2p, g_xw2);

    int nb = (n + 255) / 256;          // 196 scan blocks
    int eb = (E + 255) / 256;
    int ab = (n * 32 + 255) / 256;
    int gb = (n + 127) / 128;

    k_zero<<<nb, 256>>>((const int*)ei, 2 * E, n);
    k_deg_count<<<eb, 256>>>(ei, ew, E);
    k_scan_part<<<nb, 256>>>(n);
    k_scan_top<<<1, 256>>>(nb);
    k_downsweep<<<nb, 256>>>(n, E);
    k_scatter<<<eb, 256>>>(ei, ew, E);

    k_gemm<CHID><<<gb, 256>>>(x, W1, xw1p, n);
    k_agg1<<<ab, 256>>>(b1, n);
    k_gemm<COUT><<<gb, 256>>>(hp, W2, xw2p, n);
    k_agg2<<<ab, 256>>>(b2, out, n);
}

// round 6
// speedup vs baseline: 1.6699x; 1.1467x over previous
#include <cuda_runtime.h>
#include <math.h>
#include <stdint.h>

// N=50000, E=800000, C_IN=128, C_HID=128, C_OUT=64
#define CIN  128
#define CHID 128
#define COUT 64
#define MAXN 50048
#define MAXE 800000
#define MAXB 256   // max scan blocks (ceil(50048/256) = 196)

// -------- scratch (device globals) --------
__device__ float g_deg[MAXN];
__device__ float g_dinv[MAXN];
__device__ int   g_cnt[MAXN];
__device__ int   g_off[MAXN + 1];
__device__ int   g_cur[MAXN];
__device__ int   g_part[MAXB];
__device__ int   g_csr_src[MAXE];
__device__ float g_csr_norm[MAXE];
__device__ float g_xw1[(size_t)MAXN * CHID];
__device__ float g_h  [(size_t)MAXN * CHID];
__device__ float g_xw2[(size_t)MAXN * COUT];
__device__ int   g_idx64;

// -------- packed f32x2 helpers (base sm_100-family PTX; NOT an 'a' feature) --------
#define FMA_F32X2(d, a, b, c) \
    asm("fma.rn.f32x2 %0, %1, %2, %3;" : "=l"(d) : "l"(a), "l"(b), "l"(c))
#define PACK_DUP_F32X2(out, f) \
    asm("mov.b64 %0, {%1, %1};" : "=l"(out) : "r"(__float_as_uint(f)))
#define UNPACK_F32X2(lo, hi, in) \
    asm("mov.b64 {%0, %1}, %2;" : "=r"(lo), "=r"(hi) : "l"(in))

// -------- zero + warp-parallel edge-index width detection --------
__global__ void k_zero(const int* __restrict__ ei, int words, int n) {
    int i = blockIdx.x * blockDim.x + threadIdx.x;
    if (i < n) { g_deg[i] = 0.0f; g_cnt[i] = 0; }
    // int64 detection: little-endian int64 with small positive values => odd words zero
    if (blockIdx.x == 0 && threadIdx.x < 32) {
        int t = threadIdx.x;
        int i1 = 1 + 2 * t, i2 = 65 + 2 * t;
        int nz = 0;
        if (i1 < words && ei[i1] != 0) nz = 1;
        if (i2 < words && ei[i2] != 0) nz = 1;
        unsigned b = __ballot_sync(0xFFFFFFFFu, nz);
        if (t == 0) g_idx64 = (b == 0u) ? 1 : 0;
    }
}

__device__ __forceinline__ void edge_sd(const void* ei, int E, int e, int& s, int& d) {
    if (g_idx64) {
        const long long* p = (const long long*)ei;
        s = (int)p[e];
        d = (int)p[(size_t)E + e];
    } else {
        const int* p = (const int*)ei;
        s = p[e];
        d = p[E + e];
    }
}

__global__ void k_deg_count(const void* __restrict__ ei, const float* __restrict__ ew, int E) {
    int e = blockIdx.x * blockDim.x + threadIdx.x;
    if (e >= E) return;
    int s, d;
    edge_sd(ei, E, e, s, d);
    atomicAdd(&g_deg[d], ew[e]);
    atomicAdd(&g_cnt[d], 1);
}

// -------- parallel scan: block partial sums --------
__global__ void k_scan_part(int n) {
    __shared__ int sh[8];
    int i = blockIdx.x * 256 + threadIdx.x;
    int v = (i < n) ? g_cnt[i] : 0;
    int lane = threadIdx.x & 31, wid = threadIdx.x >> 5;
    int s = v;
#pragma unroll
    for (int o = 1; o < 32; o <<= 1) {
        int t = __shfl_up_sync(0xFFFFFFFFu, s, o);
        if (lane >= o) s += t;
    }
    if (lane == 31) sh[wid] = s;
    __syncthreads();
    if (threadIdx.x == 0) {
        int tot = 0;
#pragma unroll
        for (int w = 0; w < 8; w++) tot += sh[w];
        g_part[blockIdx.x] = tot;
    }
}

// -------- downsweep (self-computes base from partials) + fused dinv --------
__global__ void k_downsweep(int n, int E) {
    __shared__ int wsum[8], wbase[8], sh_base;
    int tid = threadIdx.x;
    int lane = tid & 31, wid = tid >> 5;
    // base = sum of partials of preceding blocks
    int acc = 0;
    for (int i = tid; i < blockIdx.x; i += 256) acc += g_part[i];
#pragma unroll
    for (int o = 16; o > 0; o >>= 1) acc += __shfl_down_sync(0xFFFFFFFFu, acc, o);
    if (lane == 0) wsum[wid] = acc;
    __syncthreads();
    if (tid == 0) {
        int b = 0;
#pragma unroll
        for (int w = 0; w < 8; w++) b += wsum[w];
        sh_base = b;
    }
    __syncthreads();

    int i = blockIdx.x * 256 + tid;
    int v = (i < n) ? g_cnt[i] : 0;
    int s = v;
#pragma unroll
    for (int o = 1; o < 32; o <<= 1) {
        int t = __shfl_up_sync(0xFFFFFFFFu, s, o);
        if (lane >= o) s += t;
    }
    if (lane == 31) wsum[wid] = s;
    __syncthreads();
    if (tid == 0) {
        int a2 = 0;
#pragma unroll
        for (int w = 0; w < 8; w++) { wbase[w] = a2; a2 += wsum[w]; }
    }
    __syncthreads();
    if (i < n) {
        int ex = sh_base + wbase[wid] + s - v;
        g_off[i] = ex;
        g_cur[i] = ex;
        g_dinv[i] = rsqrtf(g_deg[i] + 1.0f);   // +1 self loop
    }
    if (i == 0) g_off[n] = E;
}

__global__ void k_scatter(const void* __restrict__ ei, const float* __restrict__ ew, int E) {
    int e = blockIdx.x * blockDim.x + threadIdx.x;
    if (e >= E) return;
    int s, d;
    edge_sd(ei, E, e, s, d);
    int pos = atomicAdd(&g_cur[d], 1);
    g_csr_src[pos]  = s;
    g_csr_norm[pos] = g_dinv[s] * ew[e] * g_dinv[d];
}

// -------- GEMM: Y[n,NC] = X[n,128] @ W[128,NC]; 128xNC tile, packed f32x2 FMA --------
// Thread tile 8 rows x (NC/16) cols; accumulators are f32x2 pairs along ROWS, so the
// X operand pair loads directly from Xs (consecutive rows) and only W is duplicated.
template <int NC>
__launch_bounds__(256, 2)
__global__ void k_gemm(const float* __restrict__ X, const float* __restrict__ W,
                       float* __restrict__ Y, int n) {
    const int K  = 128;
    const int KB = 32;
    const int NG = NC / 64;            // column float4-groups per thread (2 for 128, 1 for 64)
    const int CT = NG * 4;             // cols per thread

    __shared__ float Ws[KB][NC];
    __shared__ float Xs[KB][132];      // [k][r], stride 132 floats (528B, 16B-aligned rows)

    int tid = threadIdx.x;
    int tx = tid & 15;                 // column lane: cols g*64 + tx*4 .. +3
    int ty = tid >> 4;                 // row group: rows ty*8 .. +7
    int row0 = blockIdx.x * 128;

    // acc[i2][j] = f32x2 over rows (ty*8 + 2*i2, ty*8 + 2*i2 + 1), col j
    unsigned long long acc[4][CT];
#pragma unroll
    for (int i = 0; i < 4; i++)
#pragma unroll
        for (int j = 0; j < CT; j++) acc[i][j] = 0ull;   // bits of (0.f, 0.f)

    for (int kt = 0; kt < K; kt += KB) {
        // W tile
        {
            const float4* W4 = (const float4*)(W + (size_t)kt * NC);
            float4* Ws4 = (float4*)&Ws[0][0];
#pragma unroll
            for (int i = tid; i < KB * NC / 4; i += 256) Ws4[i] = W4[i];
        }
        // X tile (transposed): 128 rows x 8 float4 each
#pragma unroll
        for (int i = 0; i < 4; i++) {
            int idx = tid + 256 * i;
            int r = idx >> 3, c = idx & 7;
            int row = row0 + r;
            float4 v = make_float4(0.f, 0.f, 0.f, 0.f);
            if (row < n) v = *(const float4*)&X[(size_t)row * K + kt + 4 * c];
            Xs[4 * c + 0][r] = v.x;
            Xs[4 * c + 1][r] = v.y;
            Xs[4 * c + 2][r] = v.z;
            Xs[4 * c + 3][r] = v.w;
        }
        __syncthreads();

#pragma unroll
        for (int k = 0; k < KB; k++) {
            // X row pairs: 8 consecutive floats = 4 f32x2 (16B-aligned: row stride 528B, ty*32B)
            const ulonglong2* xr2 = (const ulonglong2*)&Xs[k][ty * 8];
            ulonglong2 xa = xr2[0], xb = xr2[1];
            unsigned long long xp[4] = {xa.x, xa.y, xb.x, xb.y};
            // W values duplicated into both halves
            unsigned long long wd[CT];
#pragma unroll
            for (int g = 0; g < NG; g++) {
                float4 w4 = *(const float4*)&Ws[k][g * 64 + tx * 4];
                PACK_DUP_F32X2(wd[g * 4 + 0], w4.x);
                PACK_DUP_F32X2(wd[g * 4 + 1], w4.y);
                PACK_DUP_F32X2(wd[g * 4 + 2], w4.z);
                PACK_DUP_F32X2(wd[g * 4 + 3], w4.w);
            }
#pragma unroll
            for (int i = 0; i < 4; i++)
#pragma unroll
                for (int j = 0; j < CT; j++)
                    FMA_F32X2(acc[i][j], xp[i], wd[j], acc[i][j]);
        }
        __syncthreads();
    }

    // epilogue: unpack row pairs and store float4s
#pragma unroll
    for (int i2 = 0; i2 < 4; i2++) {
        float lo[CT], hi[CT];
#pragma unroll
        for (int j = 0; j < CT; j++) {
            uint32_t l, h;
            UNPACK_F32X2(l, h, acc[i2][j]);
            lo[j] = __uint_as_float(l);
            hi[j] = __uint_as_float(h);
        }
        int rowa = row0 + ty * 8 + 2 * i2;
        int rowb = rowa + 1;
        if (rowa < n) {
#pragma unroll
            for (int g = 0; g < NG; g++) {
                float4 o = {lo[g * 4], lo[g * 4 + 1], lo[g * 4 + 2], lo[g * 4 + 3]};
                *(float4*)&Y[(size_t)rowa * NC + g * 64 + tx * 4] = o;
            }
        }
        if (rowb < n) {
#pragma unroll
            for (int g = 0; g < NG; g++) {
                float4 o = {hi[g * 4], hi[g * 4 + 1], hi[g * 4 + 2], hi[g * 4 + 3]};
                *(float4*)&Y[(size_t)rowb * NC + g * 64 + tx * 4] = o;
            }
        }
    }
}

// -------- layer-1 aggregation (128 ch): warp per node --------
__launch_bounds__(256)
__global__ void k_agg1(const float* __restrict__ b1, int n) {
    int gw = (blockIdx.x * 256 + threadIdx.x) >> 5;
    int lane = threadIdx.x & 31;
    if (gw >= n) return;

    const float4* __restrict__ xw = (const float4*)g_xw1;
    const int*   __restrict__ csr = g_csr_src;
    const float* __restrict__ nrm = g_csr_norm;
    int beg = g_off[gw], end = g_off[gw + 1];

    float ax = 0.f, ay = 0.f, az = 0.f, aw = 0.f;
    int e = beg;
    for (; e + 2 <= end; e += 2) {
        int   s0 = __ldg(&csr[e]),  s1 = __ldg(&csr[e + 1]);
        float w0 = __ldg(&nrm[e]),  w1 = __ldg(&nrm[e + 1]);
        float4 v0 = xw[(size_t)s0 * 32 + lane];
        float4 v1 = xw[(size_t)s1 * 32 + lane];
        ax += w0 * v0.x + w1 * v1.x;
        ay += w0 * v0.y + w1 * v1.y;
        az += w0 * v0.z + w1 * v1.z;
        aw += w0 * v0.w + w1 * v1.w;
    }
    if (e < end) {
        int s = __ldg(&csr[e]);
        float w = __ldg(&nrm[e]);
        float4 v = xw[(size_t)s * 32 + lane];
        ax += w * v.x; ay += w * v.y; az += w * v.z; aw += w * v.w;
    }
    float di = g_dinv[gw];
    float sn = di * di;
    float4 vs = xw[(size_t)gw * 32 + lane];
    ax += sn * vs.x; ay += sn * vs.y; az += sn * vs.z; aw += sn * vs.w;

    float4 bb = ((const float4*)b1)[lane];
    ax += bb.x; ay += bb.y; az += bb.z; aw += bb.w;

    float4 o;
    o.x = (ax > 0.f) ? ax : expm1f(ax);
    o.y = (ay > 0.f) ? ay : expm1f(ay);
    o.z = (az > 0.f) ? az : expm1f(az);
    o.w = (aw > 0.f) ? aw : expm1f(aw);
    ((float4*)g_h)[(size_t)gw * 32 + lane] = o;
}

// -------- layer-2 aggregation (64 ch) --------
__device__ __forceinline__ float softplus_f(float v) {
    return fmaxf(v, 0.0f) + log1pf(expf(-fabsf(v)));
}

__launch_bounds__(256)
__global__ void k_agg2(const float* __restrict__ b2, float* __restrict__ out, int n) {
    int gw = (blockIdx.x * 256 + threadIdx.x) >> 5;
    int lane = threadIdx.x & 31;
    if (gw >= n) return;

    const float2* __restrict__ xw = (const float2*)g_xw2;
    const int*   __restrict__ csr = g_csr_src;
    const float* __restrict__ nrm = g_csr_norm;
    int beg = g_off[gw], end = g_off[gw + 1];

    float ax = 0.f, ay = 0.f;
    int e = beg;
    for (; e + 2 <= end; e += 2) {
        int   s0 = __ldg(&csr[e]),  s1 = __ldg(&csr[e + 1]);
        float w0 = __ldg(&nrm[e]),  w1 = __ldg(&nrm[e + 1]);
        float2 v0 = xw[(size_t)s0 * 32 + lane];
        float2 v1 = xw[(size_t)s1 * 32 + lane];
        ax += w0 * v0.x + w1 * v1.x;
        ay += w0 * v0.y + w1 * v1.y;
    }
    if (e < end) {
        int s = __ldg(&csr[e]);
        float w = __ldg(&nrm[e]);
        float2 v = xw[(size_t)s * 32 + lane];
        ax += w * v.x; ay += w * v.y;
    }
    float di = g_dinv[gw];
    float sn = di * di;
    float2 vs = xw[(size_t)gw * 32 + lane];
    ax += sn * vs.x; ay += sn * vs.y;

    float2 bb = ((const float2*)b2)[lane];
    ax += bb.x; ay += bb.y;

    float2 o;
    o.x = softplus_f(ax) + 1e-4f;
    o.y = softplus_f(ay) + 1e-4f;
    ((float2*)out)[(size_t)gw * 32 + lane] = o;
}

// -------- launcher --------
extern "C" void kernel_launch(void* const* d_in, const int* in_sizes, int n_in,
                              void* d_out, int out_size) {
    const float* x  = (const float*)d_in[0];
    const void*  ei = d_in[1];
    const float* ew = (const float*)d_in[2];
    const float* W1 = (const float*)d_in[3];
    const float* b1 = (const float*)d_in[4];
    const float* W2 = (const float*)d_in[5];
    const float* b2 = (const float*)d_in[6];
    float* out = (float*)d_out;

    int n = in_sizes[0] / CIN;   // 50000
    int E = in_sizes[2];         // 800000

    float *xw1p, *hp, *xw2p;
    cudaGetSymbolAddress((void**)&xw1p, g_xw1);
    cudaGetSymbolAddress((void**)&hp,   g_h);
    cudaGetSymbolAddress((void**)&xw2p, g_xw2);

    int nb = (n + 255) / 256;          // 196 scan blocks
    int eb = (E + 255) / 256;
    int ab = (n * 32 + 255) / 256;
    int gb = (n + 127) / 128;

    k_zero<<<nb, 256>>>((const int*)ei, 2 * E, n);
    k_deg_count<<<eb, 256>>>(ei, ew, E);
    k_scan_part<<<nb, 256>>>(n);
    k_downsweep<<<nb, 256>>>(n, E);
    k_scatter<<<eb, 256>>>(ei, ew, E);

    k_gemm<CHID><<<gb, 256>>>(x, W1, xw1p, n);
    k_agg1<<<ab, 256>>>(b1, n);
    k_gemm<COUT><<<gb, 256>>>(hp, W2, xw2p, n);
    k_agg2<<<ab, 256>>>(b2, out, n);
}

// round 8
// speedup vs baseline: 1.6880x; 1.0108x over previous
#include <cuda_runtime.h>
#include <cuda_fp16.h>
#include <math.h>
#include <stdint.h>

// N=50000, E=800000, C_IN=128, C_HID=128, C_OUT=64
#define CIN  128
#define CHID 128
#define COUT 64
#define MAXN 50048
#define MAXE 800000
#define MAXB 256   // max scan blocks (ceil(50048/256) = 196)

// -------- scratch (device globals) --------
__device__ float g_deg[MAXN];
__device__ float g_dinv[MAXN];
__device__ int   g_cnt[MAXN];
__device__ int   g_off[MAXN + 1];
__device__ int   g_cur[MAXN];
__device__ int   g_part[MAXB];
__device__ int   g_csr_src[MAXE];
__device__ float g_csr_norm[MAXE];
__device__ __half g_xw1h[(size_t)MAXN * CHID];   // x @ W1, fp16 (gathered by agg1)
__device__ float  g_h  [(size_t)MAXN * CHID];    // elu(conv1), fp32 (streamed by GEMM2)
__device__ __half g_xw2h[(size_t)MAXN * COUT];   // h @ W2, fp16 (gathered by agg2)
__device__ int   g_idx64;

// -------- packed f32x2 helpers (base sm_100-family PTX; NOT an 'a' feature) --------
#define FMA_F32X2(d, a, b, c) \
    asm("fma.rn.f32x2 %0, %1, %2, %3;" : "=l"(d) : "l"(a), "l"(b), "l"(c))
#define PACK_DUP_F32X2(out, f) \
    asm("mov.b64 %0, {%1, %1};" : "=l"(out) : "r"(__float_as_uint(f)))
#define UNPACK_F32X2(lo, hi, in) \
    asm("mov.b64 {%0, %1}, %2;" : "=r"(lo), "=r"(hi) : "l"(in))

// -------- zero + warp-parallel edge-index width detection --------
__global__ void k_zero(const int* __restrict__ ei, int words, int n) {
    int i = blockIdx.x * blockDim.x + threadIdx.x;
    if (i < n) { g_deg[i] = 0.0f; g_cnt[i] = 0; }
    if (blockIdx.x == 0 && threadIdx.x < 32) {
        int t = threadIdx.x;
        int i1 = 1 + 2 * t, i2 = 65 + 2 * t;
        int nz = 0;
        if (i1 < words && ei[i1] != 0) nz = 1;
        if (i2 < words && ei[i2] != 0) nz = 1;
        unsigned b = __ballot_sync(0xFFFFFFFFu, nz);
        if (t == 0) g_idx64 = (b == 0u) ? 1 : 0;
    }
}

__device__ __forceinline__ void edge_sd(const void* ei, int E, int e, int& s, int& d) {
    if (g_idx64) {
        const long long* p = (const long long*)ei;
        s = (int)p[e];
        d = (int)p[(size_t)E + e];
    } else {
        const int* p = (const int*)ei;
        s = p[e];
        d = p[E + e];
    }
}

__global__ void k_deg_count(const void* __restrict__ ei, const float* __restrict__ ew, int E) {
    int e = blockIdx.x * blockDim.x + threadIdx.x;
    if (e >= E) return;
    int s, d;
    edge_sd(ei, E, e, s, d);
    atomicAdd(&g_deg[d], ew[e]);
    atomicAdd(&g_cnt[d], 1);
}

// -------- parallel scan: block partial sums --------
__global__ void k_scan_part(int n) {
    __shared__ int sh[8];
    int i = blockIdx.x * 256 + threadIdx.x;
    int v = (i < n) ? g_cnt[i] : 0;
    int lane = threadIdx.x & 31, wid = threadIdx.x >> 5;
    int s = v;
#pragma unroll
    for (int o = 1; o < 32; o <<= 1) {
        int t = __shfl_up_sync(0xFFFFFFFFu, s, o);
        if (lane >= o) s += t;
    }
    if (lane == 31) sh[wid] = s;
    __syncthreads();
    if (threadIdx.x == 0) {
        int tot = 0;
#pragma unroll
        for (int w = 0; w < 8; w++) tot += sh[w];
        g_part[blockIdx.x] = tot;
    }
}

// -------- downsweep (self-computes base from partials) + fused dinv --------
__global__ void k_downsweep(int n, int E) {
    __shared__ int wsum[8], wbase[8], sh_base;
    int tid = threadIdx.x;
    int lane = tid & 31, wid = tid >> 5;
    int acc = 0;
    for (int i = tid; i < blockIdx.x; i += 256) acc += g_part[i];
#pragma unroll
    for (int o = 16; o > 0; o >>= 1) acc += __shfl_down_sync(0xFFFFFFFFu, acc, o);
    if (lane == 0) wsum[wid] = acc;
    __syncthreads();
    if (tid == 0) {
        int b = 0;
#pragma unroll
        for (int w = 0; w < 8; w++) b += wsum[w];
        sh_base = b;
    }
    __syncthreads();

    int i = blockIdx.x * 256 + tid;
    int v = (i < n) ? g_cnt[i] : 0;
    int s = v;
#pragma unroll
    for (int o = 1; o < 32; o <<= 1) {
        int t = __shfl_up_sync(0xFFFFFFFFu, s, o);
        if (lane >= o) s += t;
    }
    if (lane == 31) wsum[wid] = s;
    __syncthreads();
    if (tid == 0) {
        int a2 = 0;
#pragma unroll
        for (int w = 0; w < 8; w++) { wbase[w] = a2; a2 += wsum[w]; }
    }
    __syncthreads();
    if (i < n) {
        int ex = sh_base + wbase[wid] + s - v;
        g_off[i] = ex;
        g_cur[i] = ex;
        g_dinv[i] = rsqrtf(g_deg[i] + 1.0f);   // +1 self loop
    }
    if (i == 0) g_off[n] = E;
}

__global__ void k_scatter(const void* __restrict__ ei, const float* __restrict__ ew, int E) {
    int e = blockIdx.x * blockDim.x + threadIdx.x;
    if (e >= E) return;
    int s, d;
    edge_sd(ei, E, e, s, d);
    int pos = atomicAdd(&g_cur[d], 1);
    g_csr_src[pos]  = s;
    g_csr_norm[pos] = g_dinv[s] * ew[e] * g_dinv[d];
}

// -------- GEMM: Y[n,NC] = X[n,128] @ W[128,NC]; 128xNC tile, packed f32x2 FMA --------
// HALF_OUT: emit __half output (for gather arrays); else fp32.
template <int NC, bool HALF_OUT>
__launch_bounds__(256, 2)
__global__ void k_gemm(const float* __restrict__ X, const float* __restrict__ W,
                       void* __restrict__ Yv, int n) {
    const int K  = 128;
    const int KB = 32;
    const int NG = NC / 64;
    const int CT = NG * 4;

    __shared__ float Ws[KB][NC];
    __shared__ float Xs[KB][132];

    int tid = threadIdx.x;
    int tx = tid & 15;
    int ty = tid >> 4;
    int row0 = blockIdx.x * 128;

    unsigned long long acc[4][CT];
#pragma unroll
    for (int i = 0; i < 4; i++)
#pragma unroll
        for (int j = 0; j < CT; j++) acc[i][j] = 0ull;

    for (int kt = 0; kt < K; kt += KB) {
        {
            const float4* W4 = (const float4*)(W + (size_t)kt * NC);
            float4* Ws4 = (float4*)&Ws[0][0];
#pragma unroll
            for (int i = tid; i < KB * NC / 4; i += 256) Ws4[i] = W4[i];
        }
#pragma unroll
        for (int i = 0; i < 4; i++) {
            int idx = tid + 256 * i;
            int r = idx >> 3, c = idx & 7;
            int row = row0 + r;
            float4 v = make_float4(0.f, 0.f, 0.f, 0.f);
            if (row < n) v = *(const float4*)&X[(size_t)row * K + kt + 4 * c];
            Xs[4 * c + 0][r] = v.x;
            Xs[4 * c + 1][r] = v.y;
            Xs[4 * c + 2][r] = v.z;
            Xs[4 * c + 3][r] = v.w;
        }
        __syncthreads();

#pragma unroll
        for (int k = 0; k < KB; k++) {
            const ulonglong2* xr2 = (const ulonglong2*)&Xs[k][ty * 8];
            ulonglong2 xa = xr2[0], xb = xr2[1];
            unsigned long long xp[4] = {xa.x, xa.y, xb.x, xb.y};
            unsigned long long wd[CT];
#pragma unroll
            for (int g = 0; g < NG; g++) {
                float4 w4 = *(const float4*)&Ws[k][g * 64 + tx * 4];
                PACK_DUP_F32X2(wd[g * 4 + 0], w4.x);
                PACK_DUP_F32X2(wd[g * 4 + 1], w4.y);
                PACK_DUP_F32X2(wd[g * 4 + 2], w4.z);
                PACK_DUP_F32X2(wd[g * 4 + 3], w4.w);
            }
#pragma unroll
            for (int i = 0; i < 4; i++)
#pragma unroll
                for (int j = 0; j < CT; j++)
                    FMA_F32X2(acc[i][j], xp[i], wd[j], acc[i][j]);
        }
        __syncthreads();
    }

#pragma unroll
    for (int i2 = 0; i2 < 4; i2++) {
        float lo[CT], hi[CT];
#pragma unroll
        for (int j = 0; j < CT; j++) {
            uint32_t l, h;
            UNPACK_F32X2(l, h, acc[i2][j]);
            lo[j] = __uint_as_float(l);
            hi[j] = __uint_as_float(h);
        }
        int rowa = row0 + ty * 8 + 2 * i2;
        int rowb = rowa + 1;
        if (HALF_OUT) {
            __half* Y = (__half*)Yv;
            if (rowa < n) {
#pragma unroll
                for (int g = 0; g < NG; g++) {
                    __half2 p0 = __floats2half2_rn(lo[g * 4 + 0], lo[g * 4 + 1]);
                    __half2 p1 = __floats2half2_rn(lo[g * 4 + 2], lo[g * 4 + 3]);
                    uint2 o = {*(uint32_t*)&p0, *(uint32_t*)&p1};
                    *(uint2*)&Y[(size_t)rowa * NC + g * 64 + tx * 4] = o;
                }
            }
            if (rowb < n) {
#pragma unroll
                for (int g = 0; g < NG; g++) {
                    __half2 p0 = __floats2half2_rn(hi[g * 4 + 0], hi[g * 4 + 1]);
                    __half2 p1 = __floats2half2_rn(hi[g * 4 + 2], hi[g * 4 + 3]);
                    uint2 o = {*(uint32_t*)&p0, *(uint32_t*)&p1};
                    *(uint2*)&Y[(size_t)rowb * NC + g * 64 + tx * 4] = o;
                }
            }
        } else {
            float* Y = (float*)Yv;
            if (rowa < n) {
#pragma unroll
                for (int g = 0; g < NG; g++) {
                    float4 o = {lo[g * 4], lo[g * 4 + 1], lo[g * 4 + 2], lo[g * 4 + 3]};
                    *(float4*)&Y[(size_t)rowa * NC + g * 64 + tx * 4] = o;
                }
            }
            if (rowb < n) {
#pragma unroll
                for (int g = 0; g < NG; g++) {
                    float4 o = {hi[g * 4], hi[g * 4 + 1], hi[g * 4 + 2], hi[g * 4 + 3]};
                    *(float4*)&Y[(size_t)rowb * NC + g * 64 + tx * 4] = o;
                }
            }
        }
    }
}

// -------- layer-1 aggregation (128 ch, fp16 gathers): warp per node --------
// Row = 128 half = 32 lanes x 8B (uint2 = 2 half2).
__launch_bounds__(256)
__global__ void k_agg1(const float* __restrict__ b1, int n) {
    int gw = (blockIdx.x * 256 + threadIdx.x) >> 5;
    int lane = threadIdx.x & 31;
    if (gw >= n) return;

    const uint2* __restrict__ xw = (const uint2*)g_xw1h;
    const int*   __restrict__ csr = g_csr_src;
    const float* __restrict__ nrm = g_csr_norm;
    int beg = g_off[gw], end = g_off[gw + 1];

    float ax = 0.f, ay = 0.f, az = 0.f, aw = 0.f;
    int e = beg;
    for (; e + 2 <= end; e += 2) {
        int   s0 = __ldg(&csr[e]),  s1 = __ldg(&csr[e + 1]);
        float w0 = __ldg(&nrm[e]),  w1 = __ldg(&nrm[e + 1]);
        uint2 u0 = xw[(size_t)s0 * 32 + lane];
        uint2 u1 = xw[(size_t)s1 * 32 + lane];
        float2 a0 = __half22float2(*(__half2*)&u0.x);
        float2 b0 = __half22float2(*(__half2*)&u0.y);
        float2 a1 = __half22float2(*(__half2*)&u1.x);
        float2 b1v = __half22float2(*(__half2*)&u1.y);
        ax += w0 * a0.x + w1 * a1.x;
        ay += w0 * a0.y + w1 * a1.y;
        az += w0 * b0.x + w1 * b1v.x;
        aw += w0 * b0.y + w1 * b1v.y;
    }
    if (e < end) {
        int s = __ldg(&csr[e]);
        float w = __ldg(&nrm[e]);
        uint2 u = xw[(size_t)s * 32 + lane];
        float2 a = __half22float2(*(__half2*)&u.x);
        float2 b = __half22float2(*(__half2*)&u.y);
        ax += w * a.x; ay += w * a.y; az += w * b.x; aw += w * b.y;
    }
    float di = g_dinv[gw];
    float sn = di * di;
    {
        uint2 u = xw[(size_t)gw * 32 + lane];
        float2 a = __half22float2(*(__half2*)&u.x);
        float2 b = __half22float2(*(__half2*)&u.y);
        ax += sn * a.x; ay += sn * a.y; az += sn * b.x; aw += sn * b.y;
    }

    float4 bb = ((const float4*)b1)[lane];
    ax += bb.x; ay += bb.y; az += bb.z; aw += bb.w;

    float4 o;
    o.x = (ax > 0.f) ? ax : expm1f(ax);
    o.y = (ay > 0.f) ? ay : expm1f(ay);
    o.z = (az > 0.f) ? az : expm1f(az);
    o.w = (aw > 0.f) ? aw : expm1f(aw);
    ((float4*)g_h)[(size_t)gw * 32 + lane] = o;
}

// -------- layer-2 aggregation (64 ch, fp16 gathers) --------
__device__ __forceinline__ float softplus_f(float v) {
    return fmaxf(v, 0.0f) + log1pf(expf(-fabsf(v)));
}

// Row = 64 half = 32 lanes x 4B (half2).
__launch_bounds__(256)
__global__ void k_agg2(const float* __restrict__ b2, float* __restrict__ out, int n) {
    int gw = (blockIdx.x * 256 + threadIdx.x) >> 5;
    int lane = threadIdx.x & 31;
    if (gw >= n) return;

    const uint32_t* __restrict__ xw = (const uint32_t*)g_xw2h;
    const int*   __restrict__ csr = g_csr_src;
    const float* __restrict__ nrm = g_csr_norm;
    int beg = g_off[gw], end = g_off[gw + 1];

    float ax = 0.f, ay = 0.f;
    int e = beg;
    for (; e + 2 <= end; e += 2) {
        int   s0 = __ldg(&csr[e]),  s1 = __ldg(&csr[e + 1]);
        float w0 = __ldg(&nrm[e]),  w1 = __ldg(&nrm[e + 1]);
        uint32_t u0 = xw[(size_t)s0 * 32 + lane];
        uint32_t u1 = xw[(size_t)s1 * 32 + lane];
        float2 v0 = __half22float2(*(__half2*)&u0);
        float2 v1 = __half22float2(*(__half2*)&u1);
        ax += w0 * v0.x + w1 * v1.x;
        ay += w0 * v0.y + w1 * v1.y;
    }
    if (e < end) {
        int s = __ldg(&csr[e]);
        float w = __ldg(&nrm[e]);
        uint32_t u = xw[(size_t)s * 32 + lane];
        float2 v = __half22float2(*(__half2*)&u);
        ax += w * v.x; ay += w * v.y;
    }
    float di = g_dinv[gw];
    float sn = di * di;
    {
        uint32_t u = xw[(size_t)gw * 32 + lane];
        float2 v = __half22float2(*(__half2*)&u);
        ax += sn * v.x; ay += sn * v.y;
    }

    float2 bb = ((const float2*)b2)[lane];
    ax += bb.x; ay += bb.y;

    float2 o;
    o.x = softplus_f(ax) + 1e-4f;
    o.y = softplus_f(ay) + 1e-4f;
    ((float2*)out)[(size_t)gw * 32 + lane] = o;
}

// -------- launcher --------
extern "C" void kernel_launch(void* const* d_in, const int* in_sizes, int n_in,
                              void* d_out, int out_size) {
    const float* x  = (const float*)d_in[0];
    const void*  ei = d_in[1];
    const float* ew = (const float*)d_in[2];
    const float* W1 = (const float*)d_in[3];
    const float* b1 = (const float*)d_in[4];
    const float* W2 = (const float*)d_in[5];
    const float* b2 = (const float*)d_in[6];
    float* out = (float*)d_out;

    int n = in_sizes[0] / CIN;   // 50000
    int E = in_sizes[2];         // 800000

    void *xw1p, *hp, *xw2p;
    cudaGetSymbolAddress(&xw1p, g_xw1h);
    cudaGetSymbolAddress(&hp,   g_h);
    cudaGetSymbolAddress(&xw2p, g_xw2h);

    int nb = (n + 255) / 256;
    int eb = (E + 255) / 256;
    int ab = (n * 32 + 255) / 256;
    int gb = (n + 127) / 128;

    k_zero<<<nb, 256>>>((const int*)ei, 2 * E, n);
    k_deg_count<<<eb, 256>>>(ei, ew, E);
    k_scan_part<<<nb, 256>>>(n);
    k_downsweep<<<nb, 256>>>(n, E);
    k_scatter<<<eb, 256>>>(ei, ew, E);

    k_gemm<CHID, true><<<gb, 256>>>(x, W1, xw1p, n);
    k_agg1<<<ab, 256>>>(b1, n);
    k_gemm<COUT, true><<<gb, 256>>>((const float*)hp, W2, xw2p, n);
    k_agg2<<<ab, 256>>>(b2, out, n);
}